// round 4
// baseline (speedup 1.0000x reference)
#include <cuda_runtime.h>
#include <math.h>

#define BATCH 512
#define LEN   50
#define EMB   512
#define C1    20
#define C2    40
#define EPSV  1e-5f

// ---------------- device scratch ----------------
__device__ float g_A   [2*BATCH*C2*23];   // [side][b][o][x]
__device__ float g_s1  [C2*2*BATCH];      // [o][side][b]
__device__ float g_s2  [C2*2*BATCH];
__device__ float g_bn2 [2*C2];            // scale | shift
__device__ float g_weff[4840];            // Wfc2 @ Wfc1
__device__ float g_bias0;
__device__ float g_Wxy [2*C2*C1*3];       // Wx | Wy

__device__ __forceinline__ void ffma2(unsigned long long& d,
                                      unsigned long long a, unsigned long long b) {
    asm("fma.rn.f32x2 %0, %1, %2, %0;" : "+l"(d) : "l"(a), "l"(b));
}

// dynamic smem byte offsets
#define OFF_ES   0          // float4 es4[2][32*32]   = 32768 B
#define OFF_WS   32768      // float2 ws2[2][32*20]   = 10240 B
#define OFF_FS   43008      // float  fs[100*21]      =  8400 B
#define OFF_TOK  51408      // int    tok[100]        =   400 B
#define OFF_BN   51808      // float  bn[80]          =   320 B
#define SMEM_K1  52128
// reuse of es region after GEMM:
#define OFF_WXY  0          // float wxy[4800]
#define OFF_M    19200      // float m[1000]
#define OFF_AS   23200      // float as_[1840]

// ---------------------------------------------------------------------------
// k0: weight-only precomputes (Wxy, weff, bias0)
// ---------------------------------------------------------------------------
__global__ void k0(const float* __restrict__ W2, const float* __restrict__ Wfc1,
                   const float* __restrict__ Wfc2, const float* __restrict__ bfc1,
                   const float* __restrict__ bfc2)
{
    const int blk = blockIdx.x, tid = threadIdx.x;
    if (blk < 19) {
        int k = blk*256 + tid;
        if (k < 4840) {
            float w = 0.f;
#pragma unroll
            for (int c = 0; c < 20; c++) w += Wfc2[c]*Wfc1[c*4840 + k];
            g_weff[k] = w;
        }
        if (blk == 0 && tid == 0) {
            float z = bfc2[0];
#pragma unroll
            for (int c = 0; c < 20; c++) z += Wfc2[c]*bfc1[c];
            g_bias0 = z;
        }
    } else {
        int q = (blk - 19)*256 + tid;
        if (q < 4800) {
            int sside = q / 2400, r = q % 2400;
            int o = r / 60, rc = r % 60, c = rc / 3, d = rc % 3;
            const float* w = W2 + (o*20 + c)*9;
            g_Wxy[q] = sside ? (w[d*3+0] + w[d*3+1] + w[d*3+2])    // Wy
                             : (w[0*3+d] + w[1*3+d] + w[2*3+d]);   // Wx
        }
    }
}

// ---------------------------------------------------------------------------
// k1: block = one sample b (both sides, 100 tokens), 128 threads, 4 blocks/SM.
// gather + proj GEMM (token-packed FFMA2) + BN1 + relu + pool1 + conv1d + sums
// ---------------------------------------------------------------------------
__global__ __launch_bounds__(128, 4)
void k1(const int* __restrict__ src, const int* __restrict__ trg,
        const float* __restrict__ emb_src, const float* __restrict__ emb_trg,
        const float* __restrict__ W1, const float* __restrict__ g1,
        const float* __restrict__ beta1)
{
    extern __shared__ char smraw[];
    float4* es4 = (float4*)(smraw + OFF_ES);
    float2* ws2 = (float2*)(smraw + OFF_WS);
    float*  fs  = (float* )(smraw + OFF_FS);
    int*    tok = (int*   )(smraw + OFF_TOK);
    float*  bn  = (float* )(smraw + OFF_BN);
    float*  wxy = (float* )(smraw + OFF_WXY);
    float*  m   = (float* )(smraw + OFF_M);
    float*  as_ = (float* )(smraw + OFF_AS);

    const int tid = threadIdx.x;
    const int b  = blockIdx.x;

    if (tid < 100) {
        int u = tid / 50, l = tid % 50;
        tok[tid] = (u ? trg : src)[b*LEN + l];
    }
    __syncthreads();

    // stage one half-chunk (32 j) into buffer `buf`.
    // e stored transposed: es4[j][tq ^ ((j>>2)&7)] = float4 over 4 tokens.
    // STS.32 scatter is conflict-free: bank = (4*(tq^j4) + t3) mod 32.
    auto stage = [&](int h, int buf) {
        float* esf = (float*)(es4 + buf*1024);
#pragma unroll
        for (int it = 0; it < 7; it++) {
            int q = tid + it*128;
            if (q < 800) {
                int t = q >> 3, j4 = q & 7;
                const float* base = (t >= 50) ? emb_trg : emb_src;
                float4 v = *(const float4*)(base + (size_t)tok[t]*EMB + h*32 + j4*4);
                int tq = t >> 2, t3 = t & 3;
                int p0 = 512*j4 + 4*(tq ^ j4) + t3;   // float index, +128 per j
                esf[p0      ] = v.x;
                esf[p0 + 128] = v.y;
                esf[p0 + 256] = v.z;
                esf[p0 + 384] = v.w;
            }
        }
        float2* wb = ws2 + buf*640;
#pragma unroll
        for (int it = 0; it < 5; it++) {
            int q = tid + it*128;                     // 640 = 20c x 32j
            int c = q >> 5, j = q & 31;
            float w = W1[c*EMB + h*32 + j];
            wb[j*20 + c] = make_float2(w, w);         // duplicated for packed fma
        }
    };

    // compute tile: thread = (token-group tg of 4, channel-group cgi of 4)
    const int tg = tid / 5, cgi = tid % 5;
    const bool active = (tid < 125);

    unsigned long long acc2[8];   // [tokenpair p][channel c]
#pragma unroll
    for (int i = 0; i < 8; i++) acc2[i] = 0ULL;

    stage(0, 0);
    __syncthreads();
    for (int h = 0; h < 16; h++) {
        int buf = h & 1;
        if (h < 15) stage(h + 1, buf ^ 1);
        if (active) {
            const float4* eb = es4 + buf*1024;
            const float2* wb = ws2 + buf*640;
#pragma unroll
            for (int j = 0; j < 32; j++) {
                int swz = (j >> 2) & 7;
                ulonglong2 e   = *(const ulonglong2*)(eb + j*32 + (tg ^ swz));
                ulonglong2 w01 = *(const ulonglong2*)(wb + j*20 + cgi*4);
                ulonglong2 w23 = *(const ulonglong2*)(wb + j*20 + cgi*4 + 2);
                ffma2(acc2[0], e.x, w01.x);
                ffma2(acc2[1], e.x, w01.y);
                ffma2(acc2[2], e.x, w23.x);
                ffma2(acc2[3], e.x, w23.y);
                ffma2(acc2[4], e.y, w01.x);
                ffma2(acc2[5], e.y, w01.y);
                ffma2(acc2[6], e.y, w23.x);
                ffma2(acc2[7], e.y, w23.y);
            }
        }
        __syncthreads();
    }

    // unpack (packed along tokens: lo = even token, hi = odd token)
    if (active) {
        int t0 = tg*4, c0 = cgi*4;
#pragma unroll
        for (int p = 0; p < 2; p++)
#pragma unroll
            for (int c = 0; c < 4; c++) {
                unsigned long long v = acc2[p*4 + c];
                fs[(t0 + 2*p    )*21 + c0 + c] = __uint_as_float((unsigned)v);
                fs[(t0 + 2*p + 1)*21 + c0 + c] = __uint_as_float((unsigned)(v >> 32));
            }
    }
    __syncthreads();

    // BN1 stats per (side, channel) over 50 positions
    if (tid < 40) {
        int u = tid / 20, c = tid % 20;
        float s = 0.f, s2 = 0.f;
#pragma unroll 10
        for (int l = 0; l < 50; l++) {
            float v = fs[(u*50 + l)*21 + c];
            s += v; s2 += v*v;
        }
        float mu  = s * (1.f/50.f);
        float var = s2 * (1.f/50.f) - mu*mu;
        float sc  = g1[c] * rsqrtf(var + EPSV);
        bn[tid]      = sc;
        bn[40 + tid] = beta1[c] - mu*sc;
    }
    // load precomputed Wx|Wy (reuses es region — all reads done at loop-end sync)
    for (int q = tid; q < 4800; q += 128) wxy[q] = g_Wxy[q];
    __syncthreads();

    // BN1 apply + relu + pool1 -> m[u][c][x]
    for (int q = tid; q < 1000; q += 128) {
        int u = q / 500, r = q % 500;
        int c = r / 25, x = r % 25;
        float sc = bn[u*20 + c], sh = bn[40 + u*20 + c];
        float a0 = fs[(u*50 + 2*x    )*21 + c]*sc + sh;
        float a1 = fs[(u*50 + 2*x + 1)*21 + c]*sc + sh;
        m[u*500 + c*25 + x] = fmaxf(fmaxf(a0, a1), 0.f);
    }
    __syncthreads();

    // separable conv1d: A[u][o][x] = sum_c sum_d wxy[u][o][c][d]*m[u][c][x+d]
    for (int q = tid; q < 1840; q += 128) {
        int u = q / 920, r = q % 920;
        int o = r / 23, x = r % 23;
        const float* wb = wxy + u*2400 + o*60;
        const float* mb = m + u*500 + x;
        float acc = 0.f;
#pragma unroll
        for (int c = 0; c < 20; c++) {
            const float* w  = wb + c*3;
            const float* mm = mb + c*25;
            acc += w[0]*mm[0] + w[1]*mm[1] + w[2]*mm[2];
        }
        as_[q] = acc;
        g_A[(size_t)(u*BATCH + b)*920 + r] = acc;
    }
    __syncthreads();

    // per-sample sums for BN2 stats
    if (tid < 80) {
        int u = tid / 40, o = tid % 40;
        float s = 0.f, s2 = 0.f;
#pragma unroll
        for (int x = 0; x < 23; x++) {
            float v = as_[u*920 + o*23 + x];
            s += v; s2 += v*v;
        }
        g_s1[o*1024 + u*512 + b] = s;
        g_s2[o*1024 + u*512 + b] = s2;
    }
}

// ---------------------------------------------------------------------------
// k3: BN2 global stats from per-sample 1-D sums
// ---------------------------------------------------------------------------
__global__ void k3(const float* __restrict__ g2, const float* __restrict__ beta2)
{
    const int o = blockIdx.x, tid = threadIdx.x;
    __shared__ double rS[256], rQ[256];
    double aS = 0.0, aQ = 0.0;
    for (int b = tid; b < BATCH; b += 256) {
        double sA = g_s1[o*1024 + b],  sB = g_s1[o*1024 + 512 + b];
        double qA = g_s2[o*1024 + b],  qB = g_s2[o*1024 + 512 + b];
        aS += 23.0*(sA + sB);
        aQ += 23.0*qA + 23.0*qB + 2.0*sA*sB;
    }
    rS[tid] = aS; rQ[tid] = aQ;
    __syncthreads();
    for (int s = 128; s > 0; s >>= 1) {
        if (tid < s) { rS[tid] += rS[tid+s]; rQ[tid] += rQ[tid+s]; }
        __syncthreads();
    }
    if (tid == 0) {
        double N    = (double)BATCH * 529.0;
        double mean = rS[0] / N;
        double var  = rQ[0] / N - mean*mean;
        float  sc   = g2[o] * (float)(1.0 / sqrt(var + (double)EPSV));
        g_bn2[o]      = sc;
        g_bn2[C2 + o] = beta2[o] - (float)mean * sc;
    }
}

// ---------------------------------------------------------------------------
// kF: per sample — BN2 apply + pool2 + relu + dot(weff) + sigmoid
// ---------------------------------------------------------------------------
__global__ __launch_bounds__(256)
void kF(float* __restrict__ out)
{
    __shared__ float ua[440], vb[440], sh_s[40], red[256];
    const int b = blockIdx.x, tid = threadIdx.x;

    for (int q = tid; q < 880; q += 256) {
        int half = (q >= 440);
        int r = q - half*440;
        int o = r / 11, xx = r % 11;
        float sc = g_bn2[o];
        const float* p = &g_A[(size_t)(half*BATCH + b)*920 + o*23];
        float v = fmaxf(sc*p[2*xx], sc*p[2*xx+1]);
        (half ? vb : ua)[r] = v;
    }
    if (tid < 40) sh_s[tid] = g_bn2[C2 + tid];
    __syncthreads();

    float part = 0.f;
    for (int q = tid; q < 4840; q += 256) {
        int o = q / 121, r = q % 121, yy = r / 11, xx = r % 11;
        part += g_weff[q] * fmaxf(ua[o*11 + xx] + vb[o*11 + yy] + sh_s[o], 0.f);
    }
    red[tid] = part;
    __syncthreads();
    for (int s = 128; s > 0; s >>= 1) {
        if (tid < s) red[tid] += red[tid+s];
        __syncthreads();
    }
    if (tid == 0) out[b] = 1.f / (1.f + expf(-(red[0] + g_bias0)));
}

// ---------------------------------------------------------------------------
extern "C" void kernel_launch(void* const* d_in, const int* in_sizes, int n_in,
                              void* d_out, int out_size)
{
    const int*   src     = (const int*)  d_in[0];
    const int*   trg     = (const int*)  d_in[1];
    const float* emb_src = (const float*)d_in[3];
    const float* emb_trg = (const float*)d_in[4];
    const float* W1      = (const float*)d_in[5];
    const float* g1      = (const float*)d_in[7];
    const float* beta1   = (const float*)d_in[8];
    const float* W2      = (const float*)d_in[9];
    const float* g2      = (const float*)d_in[11];
    const float* beta2   = (const float*)d_in[12];
    const float* Wfc1    = (const float*)d_in[13];
    const float* bfc1    = (const float*)d_in[14];
    const float* Wfc2    = (const float*)d_in[15];
    const float* bfc2    = (const float*)d_in[16];

    cudaFuncSetAttribute(k1, cudaFuncAttributeMaxDynamicSharedMemorySize, SMEM_K1);

    k0<<<38, 256>>>(W2, Wfc1, Wfc2, bfc1, bfc2);
    k1<<<BATCH, 128, SMEM_K1>>>(src, trg, emb_src, emb_trg, W1, g1, beta1);
    k3<<<C2, 256>>>(g2, beta2);
    kF<<<BATCH, 256>>>((float*)d_out);
}

// round 5
// speedup vs baseline: 1.0771x; 1.0771x over previous
#include <cuda_runtime.h>
#include <math.h>

#define BATCH 512
#define LEN   50
#define EMB   512
#define C1    20
#define C2    40
#define EPSV  1e-5f

// ---------------- device scratch ----------------
__device__ float g_A   [2*BATCH*C2*23];   // [side][b][o][x]
__device__ float g_s1  [C2*2*BATCH];      // [o][side][b]
__device__ float g_s2  [C2*2*BATCH];
__device__ float g_bn2 [2*C2];            // scale | shift
__device__ float g_weff[4840];            // Wfc2 @ Wfc1
__device__ float g_bias0;
__device__ float g_Wxy [2*C2*C1*3];       // Wx | Wy

__device__ __forceinline__ void ffma2(unsigned long long& d,
                                      unsigned long long a, unsigned long long b) {
    asm("fma.rn.f32x2 %0, %1, %2, %0;" : "+l"(d) : "l"(a), "l"(b));
}

// dynamic smem layout (bytes)
#define OFF_ES   0          // float4 es4[32*32] = 16384
#define OFF_WS   16384      // float2 ws2[32*20] =  5120
#define OFF_M    21504      // float  m[1000]    =  4000
#define OFF_FS   25504      // float  fs[100*21] =  8400
#define OFF_TOK  33904      // int    tok[100]   =   400
#define OFF_BN   34304      // float  bn[80]     =   320
#define SMEM_K1  34624
// post-GEMM reuse: wxy[4800] (19200 B) at OFF 0 (inside es+ws);
//                  as_[1840] (7360 B) at OFF_FS (fs dead after pool)
#define OFF_WXY  0
#define OFF_AS   OFF_FS

// ---------------------------------------------------------------------------
// k0: weight-only precomputes (Wxy, weff, bias0)
// ---------------------------------------------------------------------------
__global__ void k0(const float* __restrict__ W2, const float* __restrict__ Wfc1,
                   const float* __restrict__ Wfc2, const float* __restrict__ bfc1,
                   const float* __restrict__ bfc2)
{
    const int blk = blockIdx.x, tid = threadIdx.x;
    if (blk < 19) {
        int k = blk*256 + tid;
        if (k < 4840) {
            float w = 0.f;
#pragma unroll
            for (int c = 0; c < 20; c++) w += Wfc2[c]*Wfc1[c*4840 + k];
            g_weff[k] = w;
        }
        if (blk == 0 && tid == 0) {
            float z = bfc2[0];
#pragma unroll
            for (int c = 0; c < 20; c++) z += Wfc2[c]*bfc1[c];
            g_bias0 = z;
        }
    } else {
        int q = (blk - 19)*256 + tid;
        if (q < 4800) {
            int sside = q / 2400, r = q % 2400;
            int o = r / 60, rc = r % 60, c = rc / 3, d = rc % 3;
            const float* w = W2 + (o*20 + c)*9;
            g_Wxy[q] = sside ? (w[d*3+0] + w[d*3+1] + w[d*3+2])    // Wy
                             : (w[0*3+d] + w[1*3+d] + w[2*3+d]);   // Wx
        }
    }
}

// ---------------------------------------------------------------------------
// k1: block = one sample (100 tokens), 128 threads, register-prefetch pipeline
// ---------------------------------------------------------------------------
__global__ __launch_bounds__(128, 5)
void k1(const int* __restrict__ src, const int* __restrict__ trg,
        const float* __restrict__ emb_src, const float* __restrict__ emb_trg,
        const float* __restrict__ W1, const float* __restrict__ g1,
        const float* __restrict__ beta1)
{
    extern __shared__ char smraw[];
    float*  esf = (float* )(smraw + OFF_ES);
    float4* es4 = (float4*)(smraw + OFF_ES);
    float2* ws2 = (float2*)(smraw + OFF_WS);
    float*  fs  = (float* )(smraw + OFF_FS);
    int*    tok = (int*   )(smraw + OFF_TOK);
    float*  bn  = (float* )(smraw + OFF_BN);
    float*  wxy = (float* )(smraw + OFF_WXY);
    float*  m   = (float* )(smraw + OFF_M);
    float*  as_ = (float* )(smraw + OFF_AS);

    const int tid = threadIdx.x;
    const int b  = blockIdx.x;

    if (tid < 100) {
        int u = tid / 50, l = tid % 50;
        tok[tid] = (u ? trg : src)[b*LEN + l];
    }
    __syncthreads();

    float4 fr[7], wr[2];

    // issue LDGs into registers (NO wait here — consumer is the STS next chunk)
    auto prefetch = [&](int h) {
#pragma unroll
        for (int it = 0; it < 7; it++) {
            int q = tid + it*128;
            if (q < 800) {
                int t = q >> 3, j4 = q & 7;
                const float* base = (t >= 50) ? emb_trg : emb_src;
                fr[it] = *(const float4*)(base + (size_t)tok[t]*EMB + h*32 + j4*4);
            }
        }
#pragma unroll
        for (int it = 0; it < 2; it++) {
            int q = tid + it*128;
            if (q < 160) {
                int c = q >> 3, j4 = q & 7;
                wr[it] = *(const float4*)(W1 + c*EMB + h*32 + j4*4);
            }
        }
    };
    // regs -> smem (transposed e with verified conflict-free XOR swizzle)
    auto store_stage = [&]() {
#pragma unroll
        for (int it = 0; it < 7; it++) {
            int q = tid + it*128;
            if (q < 800) {
                int t = q >> 3, j4 = q & 7;
                int tq = t >> 2, t3 = t & 3;
                int p0 = 512*j4 + 4*(tq ^ j4) + t3;
                esf[p0      ] = fr[it].x;
                esf[p0 + 128] = fr[it].y;
                esf[p0 + 256] = fr[it].z;
                esf[p0 + 384] = fr[it].w;
            }
        }
#pragma unroll
        for (int it = 0; it < 2; it++) {
            int q = tid + it*128;
            if (q < 160) {
                int c = q >> 3, j4 = q & 7;
                ws2[(4*j4+0)*20 + c] = make_float2(wr[it].x, wr[it].x);
                ws2[(4*j4+1)*20 + c] = make_float2(wr[it].y, wr[it].y);
                ws2[(4*j4+2)*20 + c] = make_float2(wr[it].z, wr[it].z);
                ws2[(4*j4+3)*20 + c] = make_float2(wr[it].w, wr[it].w);
            }
        }
    };

    const int tg = tid / 5, cgi = tid % 5;     // token-quad, channel-group
    const bool active = (tid < 125);

    unsigned long long acc2[8];
#pragma unroll
    for (int i = 0; i < 8; i++) acc2[i] = 0ULL;

    prefetch(0);
    for (int h = 0; h < 16; h++) {
        store_stage();                 // waits on LDGs issued one chunk ago
        __syncthreads();
        if (h < 15) prefetch(h + 1);   // LDG latency overlaps compute below
        if (active) {
#pragma unroll
            for (int j = 0; j < 32; j++) {
                int swz = (j >> 2) & 7;
                ulonglong2 e   = *(const ulonglong2*)(es4 + j*32 + (tg ^ swz));
                ulonglong2 w01 = *(const ulonglong2*)(ws2 + j*20 + cgi*4);
                ulonglong2 w23 = *(const ulonglong2*)(ws2 + j*20 + cgi*4 + 2);
                ffma2(acc2[0], e.x, w01.x);
                ffma2(acc2[1], e.x, w01.y);
                ffma2(acc2[2], e.x, w23.x);
                ffma2(acc2[3], e.x, w23.y);
                ffma2(acc2[4], e.y, w01.x);
                ffma2(acc2[5], e.y, w01.y);
                ffma2(acc2[6], e.y, w23.x);
                ffma2(acc2[7], e.y, w23.y);
            }
        }
        __syncthreads();
    }

    // unpack (packed along tokens: lo = even token, hi = odd)
    if (active) {
        int t0 = tg*4, c0 = cgi*4;
#pragma unroll
        for (int p = 0; p < 2; p++)
#pragma unroll
            for (int c = 0; c < 4; c++) {
                unsigned long long v = acc2[p*4 + c];
                fs[(t0 + 2*p    )*21 + c0 + c] = __uint_as_float((unsigned)v);
                fs[(t0 + 2*p + 1)*21 + c0 + c] = __uint_as_float((unsigned)(v >> 32));
            }
    }
    __syncthreads();

    // BN1 stats per (side, channel)
    if (tid < 40) {
        int u = tid / 20, c = tid % 20;
        float s = 0.f, s2 = 0.f;
#pragma unroll 10
        for (int l = 0; l < 50; l++) {
            float v = fs[(u*50 + l)*21 + c];
            s += v; s2 += v*v;
        }
        float mu  = s * (1.f/50.f);
        float var = s2 * (1.f/50.f) - mu*mu;
        float sc  = g1[c] * rsqrtf(var + EPSV);
        bn[tid]      = sc;
        bn[40 + tid] = beta1[c] - mu*sc;
    }
    for (int q = tid; q < 4800; q += 128) wxy[q] = g_Wxy[q];
    __syncthreads();

    // BN1 apply + relu + pool1 -> m[u][c][x]
    for (int q = tid; q < 1000; q += 128) {
        int u = q / 500, r = q % 500;
        int c = r / 25, x = r % 25;
        float sc = bn[u*20 + c], sh = bn[40 + u*20 + c];
        float a0 = fs[(u*50 + 2*x    )*21 + c]*sc + sh;
        float a1 = fs[(u*50 + 2*x + 1)*21 + c]*sc + sh;
        m[u*500 + c*25 + x] = fmaxf(fmaxf(a0, a1), 0.f);
    }
    __syncthreads();

    // separable conv1d (as_ overwrites fs region — fs dead now)
    for (int q = tid; q < 1840; q += 128) {
        int u = q / 920, r = q % 920;
        int o = r / 23, x = r % 23;
        const float* wb = wxy + u*2400 + o*60;
        const float* mb = m + u*500 + x;
        float acc = 0.f;
#pragma unroll
        for (int c = 0; c < 20; c++) {
            const float* w  = wb + c*3;
            const float* mm = mb + c*25;
            acc += w[0]*mm[0] + w[1]*mm[1] + w[2]*mm[2];
        }
        as_[q] = acc;
        g_A[(size_t)(u*BATCH + b)*920 + r] = acc;
    }
    __syncthreads();

    // per-sample sums for BN2 stats
    if (tid < 80) {
        int u = tid / 40, o = tid % 40;
        float s = 0.f, s2 = 0.f;
#pragma unroll
        for (int x = 0; x < 23; x++) {
            float v = as_[u*920 + o*23 + x];
            s += v; s2 += v*v;
        }
        g_s1[o*1024 + u*512 + b] = s;
        g_s2[o*1024 + u*512 + b] = s2;
    }
}

// ---------------------------------------------------------------------------
// k3: BN2 global stats
// ---------------------------------------------------------------------------
__global__ void k3(const float* __restrict__ g2, const float* __restrict__ beta2)
{
    const int o = blockIdx.x, tid = threadIdx.x;
    __shared__ double rS[256], rQ[256];
    double aS = 0.0, aQ = 0.0;
    for (int b = tid; b < BATCH; b += 256) {
        double sA = g_s1[o*1024 + b],  sB = g_s1[o*1024 + 512 + b];
        double qA = g_s2[o*1024 + b],  qB = g_s2[o*1024 + 512 + b];
        aS += 23.0*(sA + sB);
        aQ += 23.0*qA + 23.0*qB + 2.0*sA*sB;
    }
    rS[tid] = aS; rQ[tid] = aQ;
    __syncthreads();
    for (int s = 128; s > 0; s >>= 1) {
        if (tid < s) { rS[tid] += rS[tid+s]; rQ[tid] += rQ[tid+s]; }
        __syncthreads();
    }
    if (tid == 0) {
        double N    = (double)BATCH * 529.0;
        double mean = rS[0] / N;
        double var  = rQ[0] / N - mean*mean;
        float  sc   = g2[o] * (float)(1.0 / sqrt(var + (double)EPSV));
        g_bn2[o]      = sc;
        g_bn2[C2 + o] = beta2[o] - (float)mean * sc;
    }
}

// ---------------------------------------------------------------------------
// kF: BN2 apply + pool2 + relu + dot(weff) + sigmoid. Division-free mainloop.
// ---------------------------------------------------------------------------
__global__ __launch_bounds__(256)
void kF(float* __restrict__ out)
{
    __shared__ float ua[440], vb[440], sh_s[40], red[8];
    const int b = blockIdx.x, tid = threadIdx.x;

    for (int q = tid; q < 880; q += 256) {
        int half = (q >= 440);
        int r = q - half*440;
        int o = r / 11, xx = r - o*11;
        float sc = g_bn2[o];
        const float* p = &g_A[(size_t)(half*BATCH + b)*920 + o*23];
        (half ? vb : ua)[r] = fmaxf(sc*p[2*xx], sc*p[2*xx+1]);
    }
    if (tid < 40) sh_s[tid] = g_bn2[C2 + tid];
    __syncthreads();

    float part = 0.f;
    if (tid < 242) {
        const int half = (tid >= 121);
        const int r  = tid - half*121;           // 0..120
        const int yy = r / 11, xx = r - yy*11;   // computed ONCE
#pragma unroll
        for (int oo = 0; oo < 20; oo++) {
            int o = 2*oo + half;
            part += g_weff[o*121 + r] *
                    fmaxf(ua[o*11 + xx] + vb[o*11 + yy] + sh_s[o], 0.f);
        }
    }
#pragma unroll
    for (int off = 16; off > 0; off >>= 1)
        part += __shfl_down_sync(0xffffffffu, part, off);
    if ((tid & 31) == 0) red[tid >> 5] = part;
    __syncthreads();
    if (tid == 0) {
        float s = 0.f;
#pragma unroll
        for (int w = 0; w < 8; w++) s += red[w];
        out[b] = 1.f / (1.f + expf(-(s + g_bias0)));
    }
}

// ---------------------------------------------------------------------------
extern "C" void kernel_launch(void* const* d_in, const int* in_sizes, int n_in,
                              void* d_out, int out_size)
{
    const int*   src     = (const int*)  d_in[0];
    const int*   trg     = (const int*)  d_in[1];
    const float* emb_src = (const float*)d_in[3];
    const float* emb_trg = (const float*)d_in[4];
    const float* W1      = (const float*)d_in[5];
    const float* g1      = (const float*)d_in[7];
    const float* beta1   = (const float*)d_in[8];
    const float* W2      = (const float*)d_in[9];
    const float* g2      = (const float*)d_in[11];
    const float* beta2   = (const float*)d_in[12];
    const float* Wfc1    = (const float*)d_in[13];
    const float* bfc1    = (const float*)d_in[14];
    const float* Wfc2    = (const float*)d_in[15];
    const float* bfc2    = (const float*)d_in[16];

    cudaFuncSetAttribute(k1, cudaFuncAttributeMaxDynamicSharedMemorySize, SMEM_K1);

    k0<<<38, 256>>>(W2, Wfc1, Wfc2, bfc1, bfc2);
    k1<<<BATCH, 128, SMEM_K1>>>(src, trg, emb_src, emb_trg, W1, g1, beta1);
    k3<<<C2, 256>>>(g2, beta2);
    kF<<<BATCH, 256>>>((float*)d_out);
}

// round 6
// speedup vs baseline: 1.1109x; 1.0314x over previous
#include <cuda_runtime.h>
#include <math.h>

#define BATCH 512
#define LEN   50
#define EMB   512
#define C1    20
#define C2    40
#define EPSV  1e-5f

// ---------------- device scratch ----------------
__device__ float g_A   [2*BATCH*C2*23];   // [side][b][o][x]
__device__ float g_s1  [C2*2*BATCH];      // [o][side][b]
__device__ float g_s2  [C2*2*BATCH];
__device__ float g_bn2 [2*C2];            // scale | shift
__device__ float g_weff[4840];            // Wfc2 @ Wfc1
__device__ float g_bias0;
__device__ float g_Wxy [2*C2*C1*3];       // Wx | Wy

__device__ __forceinline__ void ffma2(unsigned long long& d,
                                      unsigned long long a, unsigned long long b) {
    asm("fma.rn.f32x2 %0, %1, %2, %0;" : "+l"(d) : "l"(a), "l"(b));
}

// dynamic smem layout (bytes) — es/ws double buffered
#define OFF_ES   0          // float4 es4[2][32*32] = 32768
#define OFF_WS   32768      // float2 ws2[2][32*20] = 10240
#define OFF_FS   43008      // float  fs[100*21]    =  8400
#define OFF_M    51408      // float  m[1000]       =  4000
#define OFF_TOK  55408      // int    tok[100]      =   400
#define OFF_BN   55808      // float  bn[80]        =   320
#define SMEM_K1  56128
#define OFF_WXY  0          // wxy[4800] reuses es after GEMM

// ---------------------------------------------------------------------------
// k0: weight-only precomputes
// ---------------------------------------------------------------------------
__global__ void k0(const float* __restrict__ W2, const float* __restrict__ Wfc1,
                   const float* __restrict__ Wfc2, const float* __restrict__ bfc1,
                   const float* __restrict__ bfc2)
{
    const int blk = blockIdx.x, tid = threadIdx.x;
    if (blk < 19) {
        int k = blk*256 + tid;
        if (k < 4840) {
            float w = 0.f;
#pragma unroll
            for (int c = 0; c < 20; c++) w += Wfc2[c]*Wfc1[c*4840 + k];
            g_weff[k] = w;
        }
        if (blk == 0 && tid == 0) {
            float z = bfc2[0];
#pragma unroll
            for (int c = 0; c < 20; c++) z += Wfc2[c]*bfc1[c];
            g_bias0 = z;
        }
    } else {
        int q = (blk - 19)*256 + tid;
        if (q < 4800) {
            int sside = q / 2400, r = q % 2400;
            int o = r / 60, rc = r % 60, c = rc / 3, d = rc % 3;
            const float* w = W2 + (o*20 + c)*9;
            g_Wxy[q] = sside ? (w[d*3+0] + w[d*3+1] + w[d*3+2])
                             : (w[0*3+d] + w[1*3+d] + w[2*3+d]);
        }
    }
}

// ---------------------------------------------------------------------------
// k1: depth-2 LDG pipeline, double-buffered smem, 1 barrier/chunk
// ---------------------------------------------------------------------------
__global__ __launch_bounds__(128, 4)
void k1(const int* __restrict__ src, const int* __restrict__ trg,
        const float* __restrict__ emb_src, const float* __restrict__ emb_trg,
        const float* __restrict__ W1, const float* __restrict__ g1,
        const float* __restrict__ beta1)
{
    extern __shared__ char smraw[];
    float*  esf = (float* )(smraw + OFF_ES);
    float4* es4 = (float4*)(smraw + OFF_ES);
    float2* ws2 = (float2*)(smraw + OFF_WS);
    float*  fs  = (float* )(smraw + OFF_FS);
    float*  m   = (float* )(smraw + OFF_M);
    int*    tok = (int*   )(smraw + OFF_TOK);
    float*  bn  = (float* )(smraw + OFF_BN);
    float*  wxy = (float* )(smraw + OFF_WXY);

    const int tid = threadIdx.x;
    const int b   = blockIdx.x;

    if (tid < 100) {
        int u = tid / 50, l = tid % 50;
        tok[tid] = (u ? trg : src)[b*LEN + l];
    }
    __syncthreads();

    // issue LDGs into a register set (no wait here)
    auto prefetch = [&](int h, float4 (&fr)[7], float4 (&wr)[2]) {
#pragma unroll
        for (int it = 0; it < 7; it++) {
            int q = tid + it*128;
            if (q < 800) {
                int t = q >> 3, j4 = q & 7;
                const float* base = (t >= 50) ? emb_trg : emb_src;
                fr[it] = *(const float4*)(base + (size_t)tok[t]*EMB + h*32 + j4*4);
            }
        }
#pragma unroll
        for (int it = 0; it < 2; it++) {
            int q = tid + it*128;
            if (q < 160) {
                int c = q >> 3, j4 = q & 7;
                wr[it] = *(const float4*)(W1 + c*EMB + h*32 + j4*4);
            }
        }
    };
    // regs -> smem buffer `buf` (conflict-free XOR swizzle, verified)
    auto store_stage = [&](float4 (&fr)[7], float4 (&wr)[2], int buf) {
        float* eb = esf + buf*4096;
        float2* wb = ws2 + buf*640;
#pragma unroll
        for (int it = 0; it < 7; it++) {
            int q = tid + it*128;
            if (q < 800) {
                int t = q >> 3, j4 = q & 7;
                int tq = t >> 2, t3 = t & 3;
                int p0 = 512*j4 + 4*(tq ^ j4) + t3;
                eb[p0      ] = fr[it].x;
                eb[p0 + 128] = fr[it].y;
                eb[p0 + 256] = fr[it].z;
                eb[p0 + 384] = fr[it].w;
            }
        }
#pragma unroll
        for (int it = 0; it < 2; it++) {
            int q = tid + it*128;
            if (q < 160) {
                int c = q >> 3, j4 = q & 7;
                wb[(4*j4+0)*20 + c] = make_float2(wr[it].x, wr[it].x);
                wb[(4*j4+1)*20 + c] = make_float2(wr[it].y, wr[it].y);
                wb[(4*j4+2)*20 + c] = make_float2(wr[it].z, wr[it].z);
                wb[(4*j4+3)*20 + c] = make_float2(wr[it].w, wr[it].w);
            }
        }
    };

    const int tg = tid / 5, cgi = tid % 5;
    const bool active = (tid < 125);

    unsigned long long acc2[8];
#pragma unroll
    for (int i = 0; i < 8; i++) acc2[i] = 0ULL;

    auto compute = [&](int buf) {
        if (!active) return;
        const float4* eb = es4 + buf*1024;
        const float2* wb = ws2 + buf*640;
#pragma unroll
        for (int j = 0; j < 32; j++) {
            int swz = (j >> 2) & 7;
            ulonglong2 e   = *(const ulonglong2*)(eb + j*32 + (tg ^ swz));
            ulonglong2 w01 = *(const ulonglong2*)(wb + j*20 + cgi*4);
            ulonglong2 w23 = *(const ulonglong2*)(wb + j*20 + cgi*4 + 2);
            ffma2(acc2[0], e.x, w01.x);
            ffma2(acc2[1], e.x, w01.y);
            ffma2(acc2[2], e.x, w23.x);
            ffma2(acc2[3], e.x, w23.y);
            ffma2(acc2[4], e.y, w01.x);
            ffma2(acc2[5], e.y, w01.y);
            ffma2(acc2[6], e.y, w23.x);
            ffma2(acc2[7], e.y, w23.y);
        }
    };

    float4 fr0[7], fr1[7], wr0[2], wr1[2];

    prefetch(0, fr0, wr0);
    prefetch(1, fr1, wr1);
    store_stage(fr0, wr0, 0);      // waits only on chunk-0 LDGs
    __syncthreads();

#pragma unroll 2
    for (int h = 0; h < 16; h++) {
        if ((h & 1) == 0) {
            if (h < 14) prefetch(h + 2, fr0, wr0);   // 2 chunks in flight
            compute(0);
            if (h < 15) store_stage(fr1, wr1, 1);    // writes OTHER buffer
        } else {
            if (h < 14) prefetch(h + 2, fr1, wr1);
            compute(1);
            if (h < 15) store_stage(fr0, wr0, 0);
        }
        __syncthreads();                              // single barrier/chunk
    }

    // unpack token-packed accumulators
    if (active) {
        int t0 = tg*4, c0 = cgi*4;
#pragma unroll
        for (int p = 0; p < 2; p++)
#pragma unroll
            for (int c = 0; c < 4; c++) {
                unsigned long long v = acc2[p*4 + c];
                fs[(t0 + 2*p    )*21 + c0 + c] = __uint_as_float((unsigned)v);
                fs[(t0 + 2*p + 1)*21 + c0 + c] = __uint_as_float((unsigned)(v >> 32));
            }
    }
    __syncthreads();

    // BN1 stats per (side, channel); wxy load in parallel (es dead)
    if (tid < 40) {
        int u = tid / 20, c = tid % 20;
        float s = 0.f, s2 = 0.f;
#pragma unroll 10
        for (int l = 0; l < 50; l++) {
            float v = fs[(u*50 + l)*21 + c];
            s += v; s2 += v*v;
        }
        float mu  = s * (1.f/50.f);
        float var = s2 * (1.f/50.f) - mu*mu;
        float sc  = g1[c] * rsqrtf(var + EPSV);
        bn[tid]      = sc;
        bn[40 + tid] = beta1[c] - mu*sc;
    }
    for (int q = tid; q < 4800; q += 128) wxy[q] = g_Wxy[q];
    __syncthreads();

    // BN1 apply + relu + pool1 -> m[u][c][x]
    for (int q = tid; q < 1000; q += 128) {
        int u = q / 500, r = q % 500;
        int c = r / 25, x = r % 25;
        float sc = bn[u*20 + c], sh = bn[40 + u*20 + c];
        float a0 = fs[(u*50 + 2*x    )*21 + c]*sc + sh;
        float a1 = fs[(u*50 + 2*x + 1)*21 + c]*sc + sh;
        m[u*500 + c*25 + x] = fmaxf(fmaxf(a0, a1), 0.f);
    }
    __syncthreads();

    // conv1d: thread = (side u, out-channel o); all 23 x in registers.
    // m-loads broadcast across o; sums fused; writes straight to gmem.
    if (tid < 80) {
        int u = tid / 40, o = tid % 40;
        const float* wb = wxy + u*2400 + o*60;
        const float* mu_ = m + u*500;
        float acc[23];
#pragma unroll
        for (int x = 0; x < 23; x++) acc[x] = 0.f;
#pragma unroll
        for (int c = 0; c < 20; c++) {
            float w0 = wb[c*3], w1 = wb[c*3+1], w2 = wb[c*3+2];
            const float* mm = mu_ + c*25;
#pragma unroll
            for (int x = 0; x < 23; x++)
                acc[x] += w0*mm[x] + w1*mm[x+1] + w2*mm[x+2];
        }
        float s = 0.f, s2 = 0.f;
        float* dst = &g_A[(size_t)(u*BATCH + b)*920 + o*23];
#pragma unroll
        for (int x = 0; x < 23; x++) {
            float v = acc[x];
            dst[x] = v; s += v; s2 += v*v;
        }
        g_s1[o*1024 + u*512 + b] = s;
        g_s2[o*1024 + u*512 + b] = s2;
    }
}

// ---------------------------------------------------------------------------
// k3: BN2 global stats
// ---------------------------------------------------------------------------
__global__ void k3(const float* __restrict__ g2, const float* __restrict__ beta2)
{
    const int o = blockIdx.x, tid = threadIdx.x;
    __shared__ double rS[256], rQ[256];
    double aS = 0.0, aQ = 0.0;
    for (int b = tid; b < BATCH; b += 256) {
        double sA = g_s1[o*1024 + b],  sB = g_s1[o*1024 + 512 + b];
        double qA = g_s2[o*1024 + b],  qB = g_s2[o*1024 + 512 + b];
        aS += 23.0*(sA + sB);
        aQ += 23.0*qA + 23.0*qB + 2.0*sA*sB;
    }
    rS[tid] = aS; rQ[tid] = aQ;
    __syncthreads();
    for (int s = 128; s > 0; s >>= 1) {
        if (tid < s) { rS[tid] += rS[tid+s]; rQ[tid] += rQ[tid+s]; }
        __syncthreads();
    }
    if (tid == 0) {
        double N    = (double)BATCH * 529.0;
        double mean = rS[0] / N;
        double var  = rQ[0] / N - mean*mean;
        float  sc   = g2[o] * (float)(1.0 / sqrt(var + (double)EPSV));
        g_bn2[o]      = sc;
        g_bn2[C2 + o] = beta2[o] - (float)mean * sc;
    }
}

// ---------------------------------------------------------------------------
// kF: BN2 apply + pool2 + relu + dot(weff) + sigmoid (division-free mainloop)
// ---------------------------------------------------------------------------
__global__ __launch_bounds__(256)
void kF(float* __restrict__ out)
{
    __shared__ float ua[440], vb[440], sh_s[40], red[8];
    const int b = blockIdx.x, tid = threadIdx.x;

    for (int q = tid; q < 880; q += 256) {
        int half = (q >= 440);
        int r = q - half*440;
        int o = r / 11, xx = r - o*11;
        float sc = g_bn2[o];
        const float* p = &g_A[(size_t)(half*BATCH + b)*920 + o*23];
        (half ? vb : ua)[r] = fmaxf(sc*p[2*xx], sc*p[2*xx+1]);
    }
    if (tid < 40) sh_s[tid] = g_bn2[C2 + tid];
    __syncthreads();

    float part = 0.f;
    if (tid < 242) {
        const int half = (tid >= 121);
        const int r  = tid - half*121;
        const int yy = r / 11, xx = r - yy*11;
#pragma unroll
        for (int oo = 0; oo < 20; oo++) {
            int o = 2*oo + half;
            part += g_weff[o*121 + r] *
                    fmaxf(ua[o*11 + xx] + vb[o*11 + yy] + sh_s[o], 0.f);
        }
    }
#pragma unroll
    for (int off = 16; off > 0; off >>= 1)
        part += __shfl_down_sync(0xffffffffu, part, off);
    if ((tid & 31) == 0) red[tid >> 5] = part;
    __syncthreads();
    if (tid == 0) {
        float s = 0.f;
#pragma unroll
        for (int w = 0; w < 8; w++) s += red[w];
        out[b] = 1.f / (1.f + expf(-(s + g_bias0)));
    }
}

// ---------------------------------------------------------------------------
extern "C" void kernel_launch(void* const* d_in, const int* in_sizes, int n_in,
                              void* d_out, int out_size)
{
    const int*   src     = (const int*)  d_in[0];
    const int*   trg     = (const int*)  d_in[1];
    const float* emb_src = (const float*)d_in[3];
    const float* emb_trg = (const float*)d_in[4];
    const float* W1      = (const float*)d_in[5];
    const float* g1      = (const float*)d_in[7];
    const float* beta1   = (const float*)d_in[8];
    const float* W2      = (const float*)d_in[9];
    const float* g2      = (const float*)d_in[11];
    const float* beta2   = (const float*)d_in[12];
    const float* Wfc1    = (const float*)d_in[13];
    const float* bfc1    = (const float*)d_in[14];
    const float* Wfc2    = (const float*)d_in[15];
    const float* bfc2    = (const float*)d_in[16];

    cudaFuncSetAttribute(k1, cudaFuncAttributeMaxDynamicSharedMemorySize, SMEM_K1);

    k0<<<38, 256>>>(W2, Wfc1, Wfc2, bfc1, bfc2);
    k1<<<BATCH, 128, SMEM_K1>>>(src, trg, emb_src, emb_trg, W1, g1, beta1);
    k3<<<C2, 256>>>(g2, beta2);
    kF<<<BATCH, 256>>>((float*)d_out);
}